// round 15
// baseline (speedup 1.0000x reference)
#include <cuda_runtime.h>
#include <cstdint>
#include <cstddef>

#define NBLK  296
#define NTHR  512
#define HTOT  592
#define BATCH 64
#define PP    196
#define ENCD  512
#define DECD  512
#define EMBD  256
#define ATTD  128
#define FFND  1024
#define VOCAB 2000
#define TT    159
#define MAXL  160
#define GIND  768
#define EPSV  1e-5f
#define NROW  12544

#define OP_OFF 0ull
#define OC_OFF 20352000ull
#define OL_OFF 20362240ull
#define OA_OFF 20362304ull
#define OO_OFF 22356800ull

// ---------------- device scratch ----------------
__device__ float g_att1t[ATTD * NROW];
__device__ float g_h1[BATCH * DECD];
__device__ float g_h2[BATCH * DECD];
__device__ float g_h1res[BATCH * DECD];
__device__ float g_h2res[BATCH * DECD];
__device__ float g_gin[BATCH * GIND];
__device__ float p_gi1[12 * BATCH * 1536];
__device__ float p_proj[12 * BATCH * 512];
__device__ float p_gh1[8 * BATCH * 1536];
__device__ float p_gh2[8 * BATCH * 1536];
__device__ float p_gi2[8 * BATCH * 1536];
__device__ float p_f1[8 * BATCH * FFND];
__device__ float p_f2[16 * BATCH * VOCAB];
__device__ float p_att2[8 * BATCH * ATTD];
__device__ float p_gg[8 * BATCH * ATTD];
__device__ unsigned g_cnt_leaf[8];
__device__ unsigned g_cnt_root;
__device__ volatile unsigned g_bsense;

struct Params {
    const float* enc;  const int* caps;  const int* lens;
    const float *eaw, *eab, *daw, *dab, *faw, *fab;
    const float *gw1, *gb1, *gw2, *gb2, *emb;
    const float *g1wih, *g1whh, *g1bih, *g1bhh;
    const float *g2wih, *g2whh, *g2bih, *g2bhh;
    const float *pw, *pb, *ln1g, *ln1b, *ln2g, *ln2b;
    const float *fw1, *fb1, *fw2, *fb2;
    float* out;
};

// Ws holds each weight DUPLICATED: Ws[kk][2n] == Ws[kk][2n+1] == w_n  (128 dup'd cols + pad)
struct SmemG { float Xs[2][16][68]; float Ws[2][16][132]; };
struct SmemA { float att2s[ATTD]; float alpha[224]; float red[16]; };

#define BARH(id) asm volatile("bar.sync %0, %1;" :: "r"(id), "r"(256) : "memory")

typedef unsigned long long u64;

__device__ __forceinline__ void ffma2(u64& d, u64 a, u64 b) {
    asm("fma.rn.f32x2 %0, %1, %2, %0;" : "+l"(d) : "l"(a), "l"(b));
}
__device__ __forceinline__ u64 dup2(float x) {
    u64 r; unsigned xi = __float_as_uint(x);
    asm("mov.b64 %0, {%1, %1};" : "=l"(r) : "r"(xi));
    return r;
}
__device__ __forceinline__ void unpk(u64 v, float& lo, float& hi) {
    unsigned a, b;
    asm("mov.b64 {%0, %1}, %2;" : "=r"(a), "=r"(b) : "l"(v));
    lo = __uint_as_float(a); hi = __uint_as_float(b);
}

// ---------------- two-level grid barrier (296 blocks = 8 leaves x 37) ----------------
__device__ __forceinline__ void gsync(unsigned& ls, int bid) {
    __syncthreads();
    if (threadIdx.x == 0) {
        ls ^= 1u;
        __threadfence();
        const int leaf = bid & 7;
        if (atomicAdd(&g_cnt_leaf[leaf], 1u) == 36u) {
            atomicExch(&g_cnt_leaf[leaf], 0u);
            if (atomicAdd(&g_cnt_root, 1u) == 7u) {
                atomicExch(&g_cnt_root, 0u);
                __threadfence();
                g_bsense = ls;
            }
        }
        while (g_bsense != ls) __nanosleep(32);
        __threadfence();
    }
    __syncthreads();
}

// ---------------- block reductions (512 threads) ----------------
__device__ __forceinline__ float bsum(float v, float* buf) {
    int lane = threadIdx.x & 31, w = threadIdx.x >> 5;
#pragma unroll
    for (int o = 16; o; o >>= 1) v += __shfl_down_sync(0xffffffffu, v, o);
    if (!lane) buf[w] = v;
    __syncthreads();
    if (threadIdx.x == 0) {
        float s = buf[0];
#pragma unroll
        for (int i = 1; i < 16; i++) s += buf[i];
        buf[0] = s;
    }
    __syncthreads();
    float r = buf[0];
    __syncthreads();
    return r;
}
__device__ __forceinline__ float bmax(float v, float* buf) {
    int lane = threadIdx.x & 31, w = threadIdx.x >> 5;
#pragma unroll
    for (int o = 16; o; o >>= 1) v = fmaxf(v, __shfl_down_sync(0xffffffffu, v, o));
    if (!lane) buf[w] = v;
    __syncthreads();
    if (threadIdx.x == 0) {
        float s = buf[0];
#pragma unroll
        for (int i = 1; i < 16; i++) s = fmaxf(s, buf[i]);
        buf[0] = s;
    }
    __syncthreads();
    float r = buf[0];
    __syncthreads();
    return r;
}
__device__ __forceinline__ float sigm(float x) { return 1.f / (1.f + expf(-x)); }

// ---------------- half-block GEMM tile: C[64 x 64] = X @ W^T ----------------
// 256 threads, microtile 4x4: acc pairs over ROWS (a-pair from Xs LDS.128),
// b duplicated in smem (no dup2 in inner loop). 11 issue slots / 16 MAC.
__device__ void gemm_tile(const float* __restrict__ X, int pstride, int nparts,
                          const float* __restrict__ xb, int ldX,
                          const float* __restrict__ W, int ldW,
                          const float* __restrict__ bias,
                          float* __restrict__ C, int ldC, int N, int transC,
                          int mbase, int nbase, int k0, int nk,
                          SmemG* sg, int barid, int ltid) {
    const int lr  = ltid >> 2;            // 0..63
    const int lk4 = (ltid & 3) << 2;      // 0,4,8,12
    const int tx  = (ltid & 15) << 2;     // 4-row group base
    const int tyc = (ltid >> 4) << 2;     // 4-col group base
    const int tyw = tyc << 1;             // float index into dup'd Ws row

    const float* Xp = X + (size_t)(mbase + lr) * ldX + k0 + lk4;
    const int wn = nbase + lr;
    const bool wok = wn < N;
    const float* Wp = W + (size_t)(wok ? wn : 0) * ldW + k0 + lk4;
    const float* xbp = xb ? xb + k0 + lk4 : nullptr;

    auto ldX4 = [&](int kt) -> float4 {
        float4 v = *(const float4*)(Xp + kt * 16);
        if (nparts > 1) {
#pragma unroll
            for (int c = 1; c < 8; c++) {
                if (c >= nparts) break;
                float4 u = *(const float4*)(Xp + (size_t)c * pstride + kt * 16);
                v.x += u.x; v.y += u.y; v.z += u.z; v.w += u.w;
            }
            const float* bb = xbp + kt * 16;
            v.x = fmaxf(v.x + bb[0], 0.f);
            v.y = fmaxf(v.y + bb[1], 0.f);
            v.z = fmaxf(v.z + bb[2], 0.f);
            v.w = fmaxf(v.w + bb[3], 0.f);
        }
        return v;
    };

    float4 xr = ldX4(0);
    float4 wr = wok ? *(const float4*)Wp : make_float4(0.f, 0.f, 0.f, 0.f);

    BARH(barid);
    sg->Xs[0][lk4+0][lr] = xr.x; sg->Xs[0][lk4+1][lr] = xr.y;
    sg->Xs[0][lk4+2][lr] = xr.z; sg->Xs[0][lk4+3][lr] = xr.w;
    *(u64*)&sg->Ws[0][lk4+0][2*lr] = dup2(wr.x);
    *(u64*)&sg->Ws[0][lk4+1][2*lr] = dup2(wr.y);
    *(u64*)&sg->Ws[0][lk4+2][2*lr] = dup2(wr.z);
    *(u64*)&sg->Ws[0][lk4+3][2*lr] = dup2(wr.w);

    u64 acc[2][4] = {};
    int buf = 0;
    for (int kt = 0; kt < nk; kt++) {
        if (kt + 1 < nk) {
            xr = ldX4(kt + 1);
            wr = wok ? *(const float4*)(Wp + (kt+1)*16) : make_float4(0.f, 0.f, 0.f, 0.f);
        }
        BARH(barid);
#pragma unroll
        for (int kk = 0; kk < 16; kk++) {
            const float4 a = *(const float4*)&sg->Xs[buf][kk][tx];
            const float4 w01 = *(const float4*)&sg->Ws[buf][kk][tyw];
            const float4 w23 = *(const float4*)&sg->Ws[buf][kk][tyw + 4];
            u64 a01, a23, b0, b1, b2, b3;
            asm("mov.b64 %0, {%1, %2};" : "=l"(a01) : "f"(a.x), "f"(a.y));
            asm("mov.b64 %0, {%1, %2};" : "=l"(a23) : "f"(a.z), "f"(a.w));
            asm("mov.b64 %0, {%1, %2};" : "=l"(b0) : "f"(w01.x), "f"(w01.y));
            asm("mov.b64 %0, {%1, %2};" : "=l"(b1) : "f"(w01.z), "f"(w01.w));
            asm("mov.b64 %0, {%1, %2};" : "=l"(b2) : "f"(w23.x), "f"(w23.y));
            asm("mov.b64 %0, {%1, %2};" : "=l"(b3) : "f"(w23.z), "f"(w23.w));
            ffma2(acc[0][0], a01, b0); ffma2(acc[0][1], a01, b1);
            ffma2(acc[0][2], a01, b2); ffma2(acc[0][3], a01, b3);
            ffma2(acc[1][0], a23, b0); ffma2(acc[1][1], a23, b1);
            ffma2(acc[1][2], a23, b2); ffma2(acc[1][3], a23, b3);
        }
        if (kt + 1 < nk) {
            int nb = buf ^ 1;
            sg->Xs[nb][lk4+0][lr] = xr.x; sg->Xs[nb][lk4+1][lr] = xr.y;
            sg->Xs[nb][lk4+2][lr] = xr.z; sg->Xs[nb][lk4+3][lr] = xr.w;
            *(u64*)&sg->Ws[nb][lk4+0][2*lr] = dup2(wr.x);
            *(u64*)&sg->Ws[nb][lk4+1][2*lr] = dup2(wr.y);
            *(u64*)&sg->Ws[nb][lk4+2][2*lr] = dup2(wr.z);
            *(u64*)&sg->Ws[nb][lk4+3][2*lr] = dup2(wr.w);
            buf = nb;
        }
    }
    // epilogue: acc[rp][c] = (row tx+2rp, row tx+2rp+1) x col (nbase+tyc+c)
#pragma unroll
    for (int rp = 0; rp < 2; rp++) {
        int gm0 = mbase + tx + rp * 2;
#pragma unroll
        for (int c = 0; c < 4; c++) {
            float lo, hi;
            unpk(acc[rp][c], lo, hi);
            int gn = nbase + tyc + c;
            if (gn < N) {
                float bz = bias ? bias[gn] : 0.f;
                if (transC) {
                    C[(size_t)gn * ldC + gm0]     = lo + bz;
                    C[(size_t)gn * ldC + gm0 + 1] = hi + bz;
                } else {
                    C[(size_t)gm0 * ldC + gn]       = lo + bz;
                    C[(size_t)(gm0 + 1) * ldC + gn] = hi + bz;
                }
            }
        }
    }
}

// ---------------- persistent kernel ----------------
__global__ void __launch_bounds__(NTHR, 2) decoder_persist(Params P) {
    extern __shared__ char dsm[];
    SmemG* G = reinterpret_cast<SmemG*>(dsm);
    SmemA* A = reinterpret_cast<SmemA*>(dsm + 2 * sizeof(SmemG));
    __shared__ int s_ord[BATCH];
    __shared__ int s_dl[BATCH];

    const int tid  = threadIdx.x;
    const int bid  = blockIdx.x;
    const int half = tid >> 8;
    const int ltid = tid & 255;
    const int barid = 1 + half;
    const int vid = bid * 2 + half;          // 0..591
    unsigned ls = g_bsense;

    if (tid < BATCH) {
        int Li = P.lens[tid];
        int r = 0;
        for (int j = 0; j < BATCH; j++) {
            int Lj = P.lens[j];
            r += (Lj > Li) || (Lj == Li && j < tid);
        }
        s_ord[r] = tid;
        s_dl[r]  = Li - 1;
    }
    __syncthreads();

    if (bid == 0) {
        if (tid < BATCH) {
            P.out[OL_OFF + tid] = (float)s_dl[tid];
            P.out[OO_OFF + tid] = (float)s_ord[tid];
        }
        for (int i = tid; i < BATCH * MAXL; i += NTHR)
            P.out[OC_OFF + i] = (float)P.caps[s_ord[i / MAXL] * MAXL + (i % MAXL)];
    }
    if (bid < BATCH) {
        g_h1[bid * DECD + tid] = 0.f;
        g_h2[bid * DECD + tid] = 0.f;
        if (tid < EMBD) {
            int cap = P.caps[s_ord[bid] * MAXL + 0];
            g_gin[bid * GIND + tid] = P.emb[(size_t)cap * EMBD + tid];
        }
    }

    // prologue: att1T (transposed), 196 m-tiles x 2 n-tiles, K=512
    for (int v = vid; v < 392; v += HTOT) {
        int mt = v >> 1, nt = v & 1;
        gemm_tile(P.enc, 0, 1, nullptr, ENCD, P.eaw, ENCD, P.eab,
                  g_att1t, NROW, ATTD, 1, mt * 64, nt * 64, 0, 32, &G[half], barid, ltid);
    }
    gsync(ls, bid);

    for (int t = 0; t < TT; t++) {
        // ===== P1: att2(16) gg(16) gh1(192) gh2(192) ffn1(t-1)(128) = 544 tiles
        for (int v = vid; v < 544; v += HTOT) {
            if (v < 16) {
                int nt = v & 1, kc = v >> 1;
                gemm_tile(g_h2, 0, 1, nullptr, DECD, P.daw, DECD, nullptr,
                          p_att2 + kc * BATCH * ATTD, ATTD, ATTD, 0,
                          0, nt * 64, kc * 64, 4, &G[half], barid, ltid);
            } else if (v < 32) {
                int u = v - 16, nt = u & 1, kc = u >> 1;
                gemm_tile(g_h2, 0, 1, nullptr, DECD, P.gw1, DECD, nullptr,
                          p_gg + kc * BATCH * ATTD, ATTD, ATTD, 0,
                          0, nt * 64, kc * 64, 4, &G[half], barid, ltid);
            } else if (v < 224) {
                int u = v - 32, nt = u >> 3, kc = u & 7;
                gemm_tile(g_h1, 0, 1, nullptr, DECD, P.g1whh, DECD, nullptr,
                          p_gh1 + kc * BATCH * 1536, 1536, 1536, 0,
                          0, nt * 64, kc * 64, 4, &G[half], barid, ltid);
            } else if (v < 416) {
                int u = v - 224, nt = u >> 3, kc = u & 7;
                gemm_tile(g_h2, 0, 1, nullptr, DECD, P.g2whh, DECD, nullptr,
                          p_gh2 + kc * BATCH * 1536, 1536, 1536, 0,
                          0, nt * 64, kc * 64, 4, &G[half], barid, ltid);
            } else if (t > 0) {
                int u = v - 416, nt = u >> 3, kc = u & 7;   // ffn1(t-1): 16nt x 8kc
                gemm_tile(g_h2res, 0, 1, nullptr, DECD, P.fw1, DECD, nullptr,
                          p_f1 + kc * BATCH * FFND, FFND, FFND, 0,
                          0, nt * 64, kc * 64, 4, &G[half], barid, ltid);
            }
        }
        gsync(ls, bid);

        // ===== P2: attention (bid<64) | ffn2a(t-1): kc 0..7, 256 tiles
        if (bid < BATCH) {
            const int b = bid, ob = s_ord[b];
            float gv = 0.f;
            if (tid < ATTD) {
                int o = b * ATTD + tid;
                float a2 = P.dab[tid], gg = P.gb1[tid];
#pragma unroll
                for (int c = 0; c < 8; c++) {
                    a2 += p_att2[c * BATCH * ATTD + o];
                    gg += p_gg[c * BATCH * ATTD + o];
                }
                A->att2s[tid] = a2;
                gv = fmaxf(gg, 0.f) * P.gw2[tid];
            }
            float gate = sigm(bsum(gv, A->red) + P.gb2[0]);

            float e = -1e30f;
            if (tid < PP) {
                const float* at = g_att1t + (size_t)ob * PP + tid;
                float s0 = 0.f, s1 = 0.f;
#pragma unroll 8
                for (int a = 0; a < ATTD; a += 2) {
                    s0 += P.faw[a]     * fmaxf(at[(size_t)a * NROW] + A->att2s[a], 0.f);
                    s1 += P.faw[a + 1] * fmaxf(at[(size_t)(a + 1) * NROW] + A->att2s[a + 1], 0.f);
                }
                e = s0 + s1 + P.fab[0];
            }
            float mx  = bmax(e, A->red);
            float ev  = (tid < PP) ? expf(e - mx) : 0.f;
            float inv = 1.f / bsum(ev, A->red);
            float mt_ = (t < s_dl[b]) ? 1.f : 0.f;
            if (tid < PP) {
                float al = ev * inv;
                A->alpha[tid] = al;
                P.out[OA_OFF + ((size_t)b * TT + t) * PP + tid] = al * mt_;
            }
            __syncthreads();

            float aw0=0.f, aw1=0.f, aw2=0.f, aw3=0.f, aw4=0.f, aw5=0.f, aw6=0.f, aw7=0.f;
            const float* eb = P.enc + (size_t)ob * PP * ENCD + tid;
            for (int p = 0; p < 192; p += 8) {
                aw0 += A->alpha[p]     * eb[(size_t)p * ENCD];
                aw1 += A->alpha[p + 1] * eb[(size_t)(p + 1) * ENCD];
                aw2 += A->alpha[p + 2] * eb[(size_t)(p + 2) * ENCD];
                aw3 += A->alpha[p + 3] * eb[(size_t)(p + 3) * ENCD];
                aw4 += A->alpha[p + 4] * eb[(size_t)(p + 4) * ENCD];
                aw5 += A->alpha[p + 5] * eb[(size_t)(p + 5) * ENCD];
                aw6 += A->alpha[p + 6] * eb[(size_t)(p + 6) * ENCD];
                aw7 += A->alpha[p + 7] * eb[(size_t)(p + 7) * ENCD];
            }
#pragma unroll
            for (int p = 192; p < 196; p++) aw0 += A->alpha[p] * eb[(size_t)p * ENCD];
            float aw = ((aw0 + aw1) + (aw2 + aw3)) + ((aw4 + aw5) + (aw6 + aw7));
            g_gin[b * GIND + EMBD + tid] = aw * gate;
        } else if (t > 0) {
            int w = (bid - BATCH) * 2 + half;          // 0..463
            if (w < 256) {
                int nt = w >> 3, kc = w & 7;           // 32nt x 8kc
                gemm_tile(p_f1, BATCH * FFND, 8, P.fb1, FFND, P.fw2, FFND, nullptr,
                          p_f2 + kc * BATCH * VOCAB, VOCAB, VOCAB, 0,
                          0, nt * 64, kc * 64, 4, &G[half], barid, ltid);
            }
        }
        gsync(ls, bid);

        // ===== P3: gi1 (288 tiles) + proj (96 tiles) = 384
        for (int v = vid; v < 384; v += HTOT) {
            if (v < 288) {
                int nt = v / 12, kc = v % 12;
                gemm_tile(g_gin, 0, 1, nullptr, GIND, P.g1wih, GIND, nullptr,
                          p_gi1 + kc * BATCH * 1536, 1536, 1536, 0,
                          0, nt * 64, kc * 64, 4, &G[half], barid, ltid);
            } else {
                int u = v - 288, nt = u / 12, kc = u % 12;
                gemm_tile(g_gin, 0, 1, nullptr, GIND, P.pw, GIND, nullptr,
                          p_proj + kc * BATCH * 512, 512, 512, 0,
                          0, nt * 64, kc * 64, 4, &G[half], barid, ltid);
            }
        }
        gsync(ls, bid);

        // ===== P4: gru1+LN1 (bid<64) | ffn2b(t-1): kc 8..15
        if (bid < BATCH) {
            const int b = bid, i = tid;
            const float mt_ = (t < s_dl[b]) ? 1.f : 0.f;
            float gir = P.g1bih[i], giz = P.g1bih[512 + i], gnn = P.g1bih[1024 + i];
#pragma unroll
            for (int c = 0; c < 12; c++) {
                int o = c * BATCH * 1536 + b * 1536;
                gir += p_gi1[o + i]; giz += p_gi1[o + 512 + i]; gnn += p_gi1[o + 1024 + i];
            }
            float ghr = P.g1bhh[i], ghz = P.g1bhh[512 + i], ghn = P.g1bhh[1024 + i];
#pragma unroll
            for (int c = 0; c < 8; c++) {
                int o = c * BATCH * 1536 + b * 1536;
                ghr += p_gh1[o + i]; ghz += p_gh1[o + 512 + i]; ghn += p_gh1[o + 1024 + i];
            }
            float pj = P.pb[i];
#pragma unroll
            for (int c = 0; c < 12; c++) pj += p_proj[c * BATCH * 512 + b * 512 + i];
            float r = sigm(gir + ghr), z = sigm(giz + ghz);
            float n = tanhf(gnn + r * ghn);
            float ho = g_h1[b * DECD + i];
            float hn = (1.f - z) * n + z * ho;
            float pr = hn + pj;
            float sum  = bsum(pr, A->red);
            float sum2 = bsum(pr * pr, A->red);
            float mean = sum * (1.f / 512.f);
            float var  = sum2 * (1.f / 512.f) - mean * mean;
            float inv  = rsqrtf(var + EPSV);
            g_h1[b * DECD + i] = (mt_ > 0.f) ? hn : ho;
            g_h1res[b * DECD + i] = (pr - mean) * inv * P.ln1g[i] + P.ln1b[i];
        } else if (t > 0) {
            int w = (bid - BATCH) * 2 + half;
            if (w < 256) {
                int nt = w >> 3, kc = 8 + (w & 7);
                gemm_tile(p_f1, BATCH * FFND, 8, P.fb1, FFND, P.fw2, FFND, nullptr,
                          p_f2 + kc * BATCH * VOCAB, VOCAB, VOCAB, 0,
                          0, nt * 64, kc * 64, 4, &G[half], barid, ltid);
            }
        }
        gsync(ls, bid);

        // ===== P5: gi2 (192 tiles) | pred-write(t-1) (64 halves)
        {
            int v = vid;
            if (v < 192) {
                int nt = v >> 3, kc = v & 7;
                gemm_tile(g_h1res, 0, 1, nullptr, DECD, P.g2wih, DECD, nullptr,
                          p_gi2 + kc * BATCH * 1536, 1536, 1536, 0,
                          0, nt * 64, kc * 64, 4, &G[half], barid, ltid);
            } else if (v < 256 && t > 0) {
                int pw_ = v - 192;
                for (int i = pw_ * 256 + ltid; i < BATCH * VOCAB; i += 64 * 256) {
                    int b = i / VOCAB, n = i - b * VOCAB;
                    float m = ((t - 1) < s_dl[b]) ? 1.f : 0.f;
                    float val = P.fb2[n];
#pragma unroll
                    for (int c = 0; c < 16; c++) val += p_f2[c * BATCH * VOCAB + i];
                    P.out[OP_OFF + ((size_t)b * TT + (t - 1)) * VOCAB + n] = val * m;
                }
            }
        }
        gsync(ls, bid);

        // ===== P6: gru2+LN2 (bid<64) | emb(t+1) writers
        if (bid < BATCH) {
            const int b = bid, i = tid;
            const float mt_ = (t < s_dl[b]) ? 1.f : 0.f;
            float gir = P.g2bih[i], giz = P.g2bih[512 + i], gnn = P.g2bih[1024 + i];
#pragma unroll
            for (int c = 0; c < 8; c++) {
                int o = c * BATCH * 1536 + b * 1536;
                gir += p_gi2[o + i]; giz += p_gi2[o + 512 + i]; gnn += p_gi2[o + 1024 + i];
            }
            float ghr = P.g2bhh[i], ghz = P.g2bhh[512 + i], ghn = P.g2bhh[1024 + i];
#pragma unroll
            for (int c = 0; c < 8; c++) {
                int o = c * BATCH * 1536 + b * 1536;
                ghr += p_gh2[o + i]; ghz += p_gh2[o + 512 + i]; ghn += p_gh2[o + 1024 + i];
            }
            float r = sigm(gir + ghr), z = sigm(giz + ghz);
            float n = tanhf(gnn + r * ghn);
            float ho = g_h2[b * DECD + i];
            float hn = (1.f - z) * n + z * ho;
            float pr = hn + g_h1res[b * DECD + i];
            float sum  = bsum(pr, A->red);
            float sum2 = bsum(pr * pr, A->red);
            float mean = sum * (1.f / 512.f);
            float var  = sum2 * (1.f / 512.f) - mean * mean;
            float inv  = rsqrtf(var + EPSV);
            g_h2[b * DECD + i] = (mt_ > 0.f) ? hn : ho;
            g_h2res[b * DECD + i] = (pr - mean) * inv * P.ln2g[i] + P.ln2b[i];
        } else if (bid < 128 && t + 1 < TT) {
            int b = bid - BATCH;
            if (tid < EMBD) {
                int cap = P.caps[s_ord[b] * MAXL + (t + 1)];
                g_gin[b * GIND + tid] = P.emb[(size_t)cap * EMBD + tid];
            }
        }
        gsync(ls, bid);
    }

    // ===== epilogue: ffn for t = 158 =====
    for (int v = vid; v < 128; v += HTOT) {
        int nt = v >> 3, kc = v & 7;
        gemm_tile(g_h2res, 0, 1, nullptr, DECD, P.fw1, DECD, nullptr,
                  p_f1 + kc * BATCH * FFND, FFND, FFND, 0,
                  0, nt * 64, kc * 64, 4, &G[half], barid, ltid);
    }
    gsync(ls, bid);
    for (int v = vid; v < 512; v += HTOT) {
        int nt = v >> 4, kc = v & 15;
        gemm_tile(p_f1, BATCH * FFND, 8, P.fb1, FFND, P.fw2, FFND, nullptr,
                  p_f2 + kc * BATCH * VOCAB, VOCAB, VOCAB, 0,
                  0, nt * 64, kc * 64, 4, &G[half], barid, ltid);
    }
    gsync(ls, bid);
    for (int i = bid * NTHR + tid; i < BATCH * VOCAB; i += NBLK * NTHR) {
        int b = i / VOCAB, n = i - b * VOCAB;
        float m = (158 < s_dl[b]) ? 1.f : 0.f;
        float val = P.fb2[n];
#pragma unroll
        for (int c = 0; c < 16; c++) val += p_f2[c * BATCH * VOCAB + i];
        P.out[OP_OFF + ((size_t)b * TT + 158) * VOCAB + n] = val * m;
    }
}

// ---------------- host ----------------
extern "C" void kernel_launch(void* const* d_in, const int* in_sizes, int n_in,
                              void* d_out, int out_size) {
    (void)in_sizes; (void)n_in; (void)out_size;
    Params p;
    p.enc   = (const float*)d_in[0];
    p.caps  = (const int*)d_in[1];
    p.lens  = (const int*)d_in[2];
    p.eaw   = (const float*)d_in[3];
    p.eab   = (const float*)d_in[4];
    p.daw   = (const float*)d_in[5];
    p.dab   = (const float*)d_in[6];
    p.faw   = (const float*)d_in[7];
    p.fab   = (const float*)d_in[8];
    p.gw1   = (const float*)d_in[9];
    p.gb1   = (const float*)d_in[10];
    p.gw2   = (const float*)d_in[11];
    p.gb2   = (const float*)d_in[12];
    p.emb   = (const float*)d_in[13];
    p.g1wih = (const float*)d_in[14];
    p.g1whh = (const float*)d_in[15];
    p.g1bih = (const float*)d_in[16];
    p.g1bhh = (const float*)d_in[17];
    p.g2wih = (const float*)d_in[18];
    p.g2whh = (const float*)d_in[19];
    p.g2bih = (const float*)d_in[20];
    p.g2bhh = (const float*)d_in[21];
    p.pw    = (const float*)d_in[22];
    p.pb    = (const float*)d_in[23];
    p.ln1g  = (const float*)d_in[24];
    p.ln1b  = (const float*)d_in[25];
    p.ln2g  = (const float*)d_in[26];
    p.ln2b  = (const float*)d_in[27];
    p.fw1   = (const float*)d_in[28];
    p.fb1   = (const float*)d_in[29];
    p.fw2   = (const float*)d_in[30];
    p.fb2   = (const float*)d_in[31];
    p.out   = (float*)d_out;

    const int smem = 2 * (int)sizeof(SmemG) + (int)sizeof(SmemA);
    cudaFuncSetAttribute(decoder_persist, cudaFuncAttributeMaxDynamicSharedMemorySize, smem);
    decoder_persist<<<NBLK, NTHR, smem>>>(p);
}

// round 16
// speedup vs baseline: 1.0511x; 1.0511x over previous
#include <cuda_runtime.h>
#include <cstdint>
#include <cstddef>

#define NBLK  296
#define NTHR  512
#define HTOT  592
#define BATCH 64
#define PP    196
#define ENCD  512
#define DECD  512
#define EMBD  256
#define ATTD  128
#define FFND  1024
#define VOCAB 2000
#define TT    159
#define MAXL  160
#define GIND  768
#define EPSV  1e-5f
#define NROW  12544

#define OP_OFF 0ull
#define OC_OFF 20352000ull
#define OL_OFF 20362240ull
#define OA_OFF 20362304ull
#define OO_OFF 22356800ull

// ---------------- device scratch ----------------
__device__ float g_att1t[ATTD * NROW];
__device__ float g_h1[BATCH * DECD];
__device__ float g_h2[BATCH * DECD];
__device__ float g_h1res[BATCH * DECD];
__device__ float g_h2res[BATCH * DECD];
__device__ float g_gin[BATCH * GIND];
__device__ float p_gi1[12 * BATCH * 1536];
__device__ float p_proj[12 * BATCH * 512];
__device__ float p_gh1[8 * BATCH * 1536];
__device__ float p_gh2[8 * BATCH * 1536];
__device__ float p_gi2[8 * BATCH * 1536];
__device__ float p_f1[8 * BATCH * FFND];
__device__ float p_f2[16 * BATCH * VOCAB];
__device__ float p_att2[8 * BATCH * ATTD];
__device__ float p_gg[8 * BATCH * ATTD];
__device__ unsigned g_cnt_leaf[8];
__device__ unsigned g_cnt_root;
__device__ volatile unsigned g_bsense;
__device__ unsigned g_gin_cnt;     // monotonic: 64 arrivals per step
__device__ unsigned g_h1res_cnt;   // monotonic: 64 arrivals per step

struct Params {
    const float* enc;  const int* caps;  const int* lens;
    const float *eaw, *eab, *daw, *dab, *faw, *fab;
    const float *gw1, *gb1, *gw2, *gb2, *emb;
    const float *g1wih, *g1whh, *g1bih, *g1bhh;
    const float *g2wih, *g2whh, *g2bih, *g2bhh;
    const float *pw, *pb, *ln1g, *ln1b, *ln2g, *ln2b;
    const float *fw1, *fb1, *fw2, *fb2;
    float* out;
};

struct SmemG { float Xs[2][16][68]; float Ws[2][16][68]; };
struct SmemA { float att2s[ATTD]; float alpha[224]; float red[16]; };

#define BARH(id) asm volatile("bar.sync %0, %1;" :: "r"(id), "r"(256) : "memory")

typedef unsigned long long u64;

__device__ __forceinline__ void ffma2(u64& d, u64 a, u64 b) {
    asm("fma.rn.f32x2 %0, %1, %2, %0;" : "+l"(d) : "l"(a), "l"(b));
}
__device__ __forceinline__ u64 dup2(float x) {
    u64 r; unsigned xi = __float_as_uint(x);
    asm("mov.b64 %0, {%1, %1};" : "=l"(r) : "r"(xi));
    return r;
}
__device__ __forceinline__ void unpk(u64 v, float& lo, float& hi) {
    unsigned a, b;
    asm("mov.b64 {%0, %1}, %2;" : "=r"(a), "=r"(b) : "l"(v));
    lo = __uint_as_float(a); hi = __uint_as_float(b);
}

// ---------------- two-level grid barrier (296 blocks = 8 leaves x 37) ----------------
__device__ __forceinline__ void gsync(unsigned& ls, int bid) {
    __syncthreads();
    if (threadIdx.x == 0) {
        ls ^= 1u;
        __threadfence();
        const int leaf = bid & 7;
        if (atomicAdd(&g_cnt_leaf[leaf], 1u) == 36u) {
            atomicExch(&g_cnt_leaf[leaf], 0u);
            if (atomicAdd(&g_cnt_root, 1u) == 7u) {
                atomicExch(&g_cnt_root, 0u);
                __threadfence();
                g_bsense = ls;
            }
        }
        while (g_bsense != ls) __nanosleep(32);
        __threadfence();
    }
    __syncthreads();
}

// ---------------- producer flags (monotonic) ----------------
__device__ __forceinline__ void flag_arrive(unsigned* cnt) {
    __threadfence();
    atomicAdd(cnt, 1u);
}
__device__ __forceinline__ void flag_wait_block(unsigned* cnt, unsigned target) {
    __syncthreads();
    if (threadIdx.x == 0) {
        while (*(volatile unsigned*)cnt < target) __nanosleep(32);
        __threadfence();
    }
    __syncthreads();
}

// ---------------- block reductions (512 threads) ----------------
__device__ __forceinline__ float bsum(float v, float* buf) {
    int lane = threadIdx.x & 31, w = threadIdx.x >> 5;
#pragma unroll
    for (int o = 16; o; o >>= 1) v += __shfl_down_sync(0xffffffffu, v, o);
    if (!lane) buf[w] = v;
    __syncthreads();
    if (threadIdx.x == 0) {
        float s = buf[0];
#pragma unroll
        for (int i = 1; i < 16; i++) s += buf[i];
        buf[0] = s;
    }
    __syncthreads();
    float r = buf[0];
    __syncthreads();
    return r;
}
__device__ __forceinline__ float bmax(float v, float* buf) {
    int lane = threadIdx.x & 31, w = threadIdx.x >> 5;
#pragma unroll
    for (int o = 16; o; o >>= 1) v = fmaxf(v, __shfl_down_sync(0xffffffffu, v, o));
    if (!lane) buf[w] = v;
    __syncthreads();
    if (threadIdx.x == 0) {
        float s = buf[0];
#pragma unroll
        for (int i = 1; i < 16; i++) s = fmaxf(s, buf[i]);
        buf[0] = s;
    }
    __syncthreads();
    float r = buf[0];
    __syncthreads();
    return r;
}
__device__ __forceinline__ float sigm(float x) { return 1.f / (1.f + expf(-x)); }

// ---------------- half-block GEMM tile: C[64 x 64] = X @ W^T (R14 inner loop) ----------------
__device__ void gemm_tile(const float* __restrict__ X, int pstride, int nparts,
                          const float* __restrict__ xb, int ldX,
                          const float* __restrict__ W, int ldW,
                          const float* __restrict__ bias,
                          float* __restrict__ C, int ldC, int N, int transC,
                          int mbase, int nbase, int k0, int nk,
                          SmemG* sg, int barid, int ltid) {
    const int lr  = ltid >> 2;
    const int lk4 = (ltid & 3) << 2;
    const int tx  = (ltid & 15) << 2;
    const int ty  = (ltid >> 4) << 2;

    const float* Xp = X + (size_t)(mbase + lr) * ldX + k0 + lk4;
    const int wn = nbase + lr;
    const bool wok = wn < N;
    const float* Wp = W + (size_t)(wok ? wn : 0) * ldW + k0 + lk4;
    const float* xbp = xb ? xb + k0 + lk4 : nullptr;

    auto ldX4 = [&](int kt) -> float4 {
        float4 v = *(const float4*)(Xp + kt * 16);
        if (nparts > 1) {
#pragma unroll
            for (int c = 1; c < 8; c++) {
                if (c >= nparts) break;
                float4 u = *(const float4*)(Xp + (size_t)c * pstride + kt * 16);
                v.x += u.x; v.y += u.y; v.z += u.z; v.w += u.w;
            }
            const float* bb = xbp + kt * 16;
            v.x = fmaxf(v.x + bb[0], 0.f);
            v.y = fmaxf(v.y + bb[1], 0.f);
            v.z = fmaxf(v.z + bb[2], 0.f);
            v.w = fmaxf(v.w + bb[3], 0.f);
        }
        return v;
    };

    float4 xr = ldX4(0);
    float4 wr = wok ? *(const float4*)Wp : make_float4(0.f, 0.f, 0.f, 0.f);

    BARH(barid);
    sg->Xs[0][lk4+0][lr] = xr.x; sg->Xs[0][lk4+1][lr] = xr.y;
    sg->Xs[0][lk4+2][lr] = xr.z; sg->Xs[0][lk4+3][lr] = xr.w;
    sg->Ws[0][lk4+0][lr] = wr.x; sg->Ws[0][lk4+1][lr] = wr.y;
    sg->Ws[0][lk4+2][lr] = wr.z; sg->Ws[0][lk4+3][lr] = wr.w;

    u64 acc[4][2] = {};
    int buf = 0;
    for (int kt = 0; kt < nk; kt++) {
        if (kt + 1 < nk) {
            xr = ldX4(kt + 1);
            wr = wok ? *(const float4*)(Wp + (kt+1)*16) : make_float4(0.f, 0.f, 0.f, 0.f);
        }
        BARH(barid);
#pragma unroll
        for (int kk = 0; kk < 16; kk++) {
            const float4 a = *(const float4*)&sg->Xs[buf][kk][tx];
            const u64* wp = (const u64*)&sg->Ws[buf][kk][ty];
            u64 b0 = wp[0], b1 = wp[1];
            u64 pa;
            pa = dup2(a.x); ffma2(acc[0][0], pa, b0); ffma2(acc[0][1], pa, b1);
            pa = dup2(a.y); ffma2(acc[1][0], pa, b0); ffma2(acc[1][1], pa, b1);
            pa = dup2(a.z); ffma2(acc[2][0], pa, b0); ffma2(acc[2][1], pa, b1);
            pa = dup2(a.w); ffma2(acc[3][0], pa, b0); ffma2(acc[3][1], pa, b1);
        }
        if (kt + 1 < nk) {
            int nb = buf ^ 1;
            sg->Xs[nb][lk4+0][lr] = xr.x; sg->Xs[nb][lk4+1][lr] = xr.y;
            sg->Xs[nb][lk4+2][lr] = xr.z; sg->Xs[nb][lk4+3][lr] = xr.w;
            sg->Ws[nb][lk4+0][lr] = wr.x; sg->Ws[nb][lk4+1][lr] = wr.y;
            sg->Ws[nb][lk4+2][lr] = wr.z; sg->Ws[nb][lk4+3][lr] = wr.w;
            buf = nb;
        }
    }
#pragma unroll
    for (int i = 0; i < 4; i++) {
        int gm = mbase + tx + i;
#pragma unroll
        for (int jp = 0; jp < 2; jp++) {
            float lo, hi;
            unpk(acc[i][jp], lo, hi);
            int gn = nbase + ty + 2*jp;
            if (gn < N) {
                float v = lo + (bias ? bias[gn] : 0.f);
                if (transC) C[(size_t)gn * ldC + gm] = v; else C[(size_t)gm * ldC + gn] = v;
            }
            if (gn + 1 < N) {
                float v = hi + (bias ? bias[gn+1] : 0.f);
                if (transC) C[(size_t)(gn+1) * ldC + gm] = v; else C[(size_t)gm * ldC + gn + 1] = v;
            }
        }
    }
}

// ---------------- persistent kernel ----------------
__global__ void __launch_bounds__(NTHR, 2) decoder_persist(Params P) {
    extern __shared__ char dsm[];
    SmemG* G = reinterpret_cast<SmemG*>(dsm);
    SmemA* A = reinterpret_cast<SmemA*>(dsm + 2 * sizeof(SmemG));
    __shared__ int s_ord[BATCH];
    __shared__ int s_dl[BATCH];

    const int tid  = threadIdx.x;
    const int bid  = blockIdx.x;
    const int half = tid >> 8;
    const int ltid = tid & 255;
    const int barid = 1 + half;
    const int vid = bid * 2 + half;                  // 0..591
    const int wv  = (bid - BATCH) * 2 + half;        // worker half id 0..463 (bid>=64)
    unsigned ls = g_bsense;

    if (tid < BATCH) {
        int Li = P.lens[tid];
        int r = 0;
        for (int j = 0; j < BATCH; j++) {
            int Lj = P.lens[j];
            r += (Lj > Li) || (Lj == Li && j < tid);
        }
        s_ord[r] = tid;
        s_dl[r]  = Li - 1;
    }
    __syncthreads();

    if (bid == 0) {
        if (tid == 0) { g_gin_cnt = 0u; g_h1res_cnt = 0u; }
        if (tid < BATCH) {
            P.out[OL_OFF + tid] = (float)s_dl[tid];
            P.out[OO_OFF + tid] = (float)s_ord[tid];
        }
        for (int i = tid; i < BATCH * MAXL; i += NTHR)
            P.out[OC_OFF + i] = (float)P.caps[s_ord[i / MAXL] * MAXL + (i % MAXL)];
    }
    if (bid < BATCH) {
        g_h1[bid * DECD + tid] = 0.f;
        g_h2[bid * DECD + tid] = 0.f;
        if (tid < EMBD) {
            int cap = P.caps[s_ord[bid] * MAXL + 0];
            g_gin[bid * GIND + tid] = P.emb[(size_t)cap * EMBD + tid];
        }
    }

    // prologue: att1T (transposed), 196 m-tiles x 2 n-tiles, K=512
    for (int v = vid; v < 392; v += HTOT) {
        int mt = v >> 1, nt = v & 1;
        gemm_tile(P.enc, 0, 1, nullptr, ENCD, P.eaw, ENCD, P.eab,
                  g_att1t, NROW, ATTD, 1, mt * 64, nt * 64, 0, 32, &G[half], barid, ltid);
    }
    gsync(ls, bid);   // also publishes the counter resets

    for (int t = 0; t < TT; t++) {
        // ===== P1: att2(16) gg(16) gh1(192) gh2(192) ffn1(t-1)(128) = 544 tiles
        for (int v = vid; v < 544; v += HTOT) {
            if (v < 16) {
                int nt = v & 1, kc = v >> 1;
                gemm_tile(g_h2, 0, 1, nullptr, DECD, P.daw, DECD, nullptr,
                          p_att2 + kc * BATCH * ATTD, ATTD, ATTD, 0,
                          0, nt * 64, kc * 64, 4, &G[half], barid, ltid);
            } else if (v < 32) {
                int u = v - 16, nt = u & 1, kc = u >> 1;
                gemm_tile(g_h2, 0, 1, nullptr, DECD, P.gw1, DECD, nullptr,
                          p_gg + kc * BATCH * ATTD, ATTD, ATTD, 0,
                          0, nt * 64, kc * 64, 4, &G[half], barid, ltid);
            } else if (v < 224) {
                int u = v - 32, nt = u >> 3, kc = u & 7;
                gemm_tile(g_h1, 0, 1, nullptr, DECD, P.g1whh, DECD, nullptr,
                          p_gh1 + kc * BATCH * 1536, 1536, 1536, 0,
                          0, nt * 64, kc * 64, 4, &G[half], barid, ltid);
            } else if (v < 416) {
                int u = v - 224, nt = u >> 3, kc = u & 7;
                gemm_tile(g_h2, 0, 1, nullptr, DECD, P.g2whh, DECD, nullptr,
                          p_gh2 + kc * BATCH * 1536, 1536, 1536, 0,
                          0, nt * 64, kc * 64, 4, &G[half], barid, ltid);
            } else if (t > 0) {
                int u = v - 416, nt = u >> 3, kc = u & 7;
                gemm_tile(g_h2res, 0, 1, nullptr, DECD, P.fw1, DECD, nullptr,
                          p_f1 + kc * BATCH * FFND, FFND, FFND, 0,
                          0, nt * 64, kc * 64, 4, &G[half], barid, ltid);
            }
        }
        gsync(ls, bid);

        // ===== P2: attention (bid<64, then flag) | workers: ffn2a(t-1) -> wait gin -> gi1+proj
        if (bid < BATCH) {
            const int b = bid, ob = s_ord[b];
            float gv = 0.f;
            if (tid < ATTD) {
                int o = b * ATTD + tid;
                float a2 = P.dab[tid], gg = P.gb1[tid];
#pragma unroll
                for (int c = 0; c < 8; c++) {
                    a2 += p_att2[c * BATCH * ATTD + o];
                    gg += p_gg[c * BATCH * ATTD + o];
                }
                A->att2s[tid] = a2;
                gv = fmaxf(gg, 0.f) * P.gw2[tid];
            }
            float gate = sigm(bsum(gv, A->red) + P.gb2[0]);

            float e = -1e30f;
            if (tid < PP) {
                const float* at = g_att1t + (size_t)ob * PP + tid;
                float s0 = 0.f, s1 = 0.f;
#pragma unroll 8
                for (int a = 0; a < ATTD; a += 2) {
                    s0 += P.faw[a]     * fmaxf(at[(size_t)a * NROW] + A->att2s[a], 0.f);
                    s1 += P.faw[a + 1] * fmaxf(at[(size_t)(a + 1) * NROW] + A->att2s[a + 1], 0.f);
                }
                e = s0 + s1 + P.fab[0];
            }
            float mx  = bmax(e, A->red);
            float ev  = (tid < PP) ? expf(e - mx) : 0.f;
            float inv = 1.f / bsum(ev, A->red);
            float mt_ = (t < s_dl[b]) ? 1.f : 0.f;
            if (tid < PP) {
                float al = ev * inv;
                A->alpha[tid] = al;
                P.out[OA_OFF + ((size_t)b * TT + t) * PP + tid] = al * mt_;
            }
            __syncthreads();

            float aw0=0.f, aw1=0.f, aw2=0.f, aw3=0.f, aw4=0.f, aw5=0.f, aw6=0.f, aw7=0.f;
            const float* eb = P.enc + (size_t)ob * PP * ENCD + tid;
            for (int p = 0; p < 192; p += 8) {
                aw0 += A->alpha[p]     * eb[(size_t)p * ENCD];
                aw1 += A->alpha[p + 1] * eb[(size_t)(p + 1) * ENCD];
                aw2 += A->alpha[p + 2] * eb[(size_t)(p + 2) * ENCD];
                aw3 += A->alpha[p + 3] * eb[(size_t)(p + 3) * ENCD];
                aw4 += A->alpha[p + 4] * eb[(size_t)(p + 4) * ENCD];
                aw5 += A->alpha[p + 5] * eb[(size_t)(p + 5) * ENCD];
                aw6 += A->alpha[p + 6] * eb[(size_t)(p + 6) * ENCD];
                aw7 += A->alpha[p + 7] * eb[(size_t)(p + 7) * ENCD];
            }
#pragma unroll
            for (int p = 192; p < 196; p++) aw0 += A->alpha[p] * eb[(size_t)p * ENCD];
            float aw = ((aw0 + aw1) + (aw2 + aw3)) + ((aw4 + aw5) + (aw6 + aw7));
            g_gin[b * GIND + EMBD + tid] = aw * gate;
            __syncthreads();
            if (tid == 0) flag_arrive(&g_gin_cnt);
        } else {
            if (t > 0 && wv < 256) {
                int nt = wv >> 3, kc = wv & 7;
                gemm_tile(p_f1, BATCH * FFND, 8, P.fb1, FFND, P.fw2, FFND, nullptr,
                          p_f2 + kc * BATCH * VOCAB, VOCAB, VOCAB, 0,
                          0, nt * 64, kc * 64, 4, &G[half], barid, ltid);
            }
            flag_wait_block(&g_gin_cnt, 64u * (unsigned)(t + 1));
            if (wv < 288) {
                int nt = wv / 12, kc = wv % 12;
                gemm_tile(g_gin, 0, 1, nullptr, GIND, P.g1wih, GIND, nullptr,
                          p_gi1 + kc * BATCH * 1536, 1536, 1536, 0,
                          0, nt * 64, kc * 64, 4, &G[half], barid, ltid);
            } else if (wv < 384) {
                int u = wv - 288, nt = u / 12, kc = u % 12;
                gemm_tile(g_gin, 0, 1, nullptr, GIND, P.pw, GIND, nullptr,
                          p_proj + kc * BATCH * 512, 512, 512, 0,
                          0, nt * 64, kc * 64, 4, &G[half], barid, ltid);
            }
        }
        gsync(ls, bid);

        // ===== P3: gru1+LN1 (bid<64, then flag) | workers: ffn2b(t-1) -> wait h1res -> gi2
        if (bid < BATCH) {
            const int b = bid, i = tid;
            const float mt_ = (t < s_dl[b]) ? 1.f : 0.f;
            float gir = P.g1bih[i], giz = P.g1bih[512 + i], gnn = P.g1bih[1024 + i];
#pragma unroll
            for (int c = 0; c < 12; c++) {
                int o = c * BATCH * 1536 + b * 1536;
                gir += p_gi1[o + i]; giz += p_gi1[o + 512 + i]; gnn += p_gi1[o + 1024 + i];
            }
            float ghr = P.g1bhh[i], ghz = P.g1bhh[512 + i], ghn = P.g1bhh[1024 + i];
#pragma unroll
            for (int c = 0; c < 8; c++) {
                int o = c * BATCH * 1536 + b * 1536;
                ghr += p_gh1[o + i]; ghz += p_gh1[o + 512 + i]; ghn += p_gh1[o + 1024 + i];
            }
            float pj = P.pb[i];
#pragma unroll
            for (int c = 0; c < 12; c++) pj += p_proj[c * BATCH * 512 + b * 512 + i];
            float r = sigm(gir + ghr), z = sigm(giz + ghz);
            float n = tanhf(gnn + r * ghn);
            float ho = g_h1[b * DECD + i];
            float hn = (1.f - z) * n + z * ho;
            float pr = hn + pj;
            float sum  = bsum(pr, A->red);
            float sum2 = bsum(pr * pr, A->red);
            float mean = sum * (1.f / 512.f);
            float var  = sum2 * (1.f / 512.f) - mean * mean;
            float inv  = rsqrtf(var + EPSV);
            g_h1[b * DECD + i] = (mt_ > 0.f) ? hn : ho;
            g_h1res[b * DECD + i] = (pr - mean) * inv * P.ln1g[i] + P.ln1b[i];
            __syncthreads();
            if (tid == 0) flag_arrive(&g_h1res_cnt);
        } else {
            if (t > 0 && wv < 256) {
                int nt = wv >> 3, kc = 8 + (wv & 7);
                gemm_tile(p_f1, BATCH * FFND, 8, P.fb1, FFND, P.fw2, FFND, nullptr,
                          p_f2 + kc * BATCH * VOCAB, VOCAB, VOCAB, 0,
                          0, nt * 64, kc * 64, 4, &G[half], barid, ltid);
            }
            flag_wait_block(&g_h1res_cnt, 64u * (unsigned)(t + 1));
            if (wv < 192) {
                int nt = wv >> 3, kc = wv & 7;
                gemm_tile(g_h1res, 0, 1, nullptr, DECD, P.g2wih, DECD, nullptr,
                          p_gi2 + kc * BATCH * 1536, 1536, 1536, 0,
                          0, nt * 64, kc * 64, 4, &G[half], barid, ltid);
            }
        }
        gsync(ls, bid);

        // ===== P4: gru2+LN2 (bid<64) | workers: pred-write(t-1) + emb(t+1)
        if (bid < BATCH) {
            const int b = bid, i = tid;
            const float mt_ = (t < s_dl[b]) ? 1.f : 0.f;
            float gir = P.g2bih[i], giz = P.g2bih[512 + i], gnn = P.g2bih[1024 + i];
#pragma unroll
            for (int c = 0; c < 8; c++) {
                int o = c * BATCH * 1536 + b * 1536;
                gir += p_gi2[o + i]; giz += p_gi2[o + 512 + i]; gnn += p_gi2[o + 1024 + i];
            }
            float ghr = P.g2bhh[i], ghz = P.g2bhh[512 + i], ghn = P.g2bhh[1024 + i];
#pragma unroll
            for (int c = 0; c < 8; c++) {
                int o = c * BATCH * 1536 + b * 1536;
                ghr += p_gh2[o + i]; ghz += p_gh2[o + 512 + i]; ghn += p_gh2[o + 1024 + i];
            }
            float r = sigm(gir + ghr), z = sigm(giz + ghz);
            float n = tanhf(gnn + r * ghn);
            float ho = g_h2[b * DECD + i];
            float hn = (1.f - z) * n + z * ho;
            float pr = hn + g_h1res[b * DECD + i];
            float sum  = bsum(pr, A->red);
            float sum2 = bsum(pr * pr, A->red);
            float mean = sum * (1.f / 512.f);
            float var  = sum2 * (1.f / 512.f) - mean * mean;
            float inv  = rsqrtf(var + EPSV);
            g_h2[b * DECD + i] = (mt_ > 0.f) ? hn : ho;
            g_h2res[b * DECD + i] = (pr - mean) * inv * P.ln2g[i] + P.ln2b[i];
        } else {
            if (t > 0 && wv < 64) {
                for (int i = wv * 256 + ltid; i < BATCH * VOCAB; i += 64 * 256) {
                    int b = i / VOCAB, n = i - b * VOCAB;
                    float m = ((t - 1) < s_dl[b]) ? 1.f : 0.f;
                    float val = P.fb2[n];
#pragma unroll
                    for (int c = 0; c < 16; c++) val += p_f2[c * BATCH * VOCAB + i];
                    P.out[OP_OFF + ((size_t)b * TT + (t - 1)) * VOCAB + n] = val * m;
                }
            } else if (wv >= 64 && wv < 128 && t + 1 < TT) {
                int b = wv - 64;
                if (ltid < 128) {
                    // two halves of 128 threads each cover 256 emb cols? ltid<128: cols via ltid*2
                    int c0 = ltid * 2;
                    int cap = P.caps[s_ord[b] * MAXL + (t + 1)];
                    g_gin[b * GIND + c0]     = P.emb[(size_t)cap * EMBD + c0];
                    g_gin[b * GIND + c0 + 1] = P.emb[(size_t)cap * EMBD + c0 + 1];
                }
            }
        }
        gsync(ls, bid);
    }

    // ===== epilogue: ffn for t = 158 =====
    for (int v = vid; v < 128; v += HTOT) {
        int nt = v >> 3, kc = v & 7;
        gemm_tile(g_h2res, 0, 1, nullptr, DECD, P.fw1, DECD, nullptr,
                  p_f1 + kc * BATCH * FFND, FFND, FFND, 0,
                  0, nt * 64, kc * 64, 4, &G[half], barid, ltid);
    }
    gsync(ls, bid);
    for (int v = vid; v < 512; v += HTOT) {
        int nt = v >> 4, kc = v & 15;
        gemm_tile(p_f1, BATCH * FFND, 8, P.fb1, FFND, P.fw2, FFND, nullptr,
                  p_f2 + kc * BATCH * VOCAB, VOCAB, VOCAB, 0,
                  0, nt * 64, kc * 64, 4, &G[half], barid, ltid);
    }
    gsync(ls, bid);
    for (int i = bid * NTHR + tid; i < BATCH * VOCAB; i += NBLK * NTHR) {
        int b = i / VOCAB, n = i - b * VOCAB;
        float m = (158 < s_dl[b]) ? 1.f : 0.f;
        float val = P.fb2[n];
#pragma unroll
        for (int c = 0; c < 16; c++) val += p_f2[c * BATCH * VOCAB + i];
        P.out[OP_OFF + ((size_t)b * TT + 158) * VOCAB + n] = val * m;
    }
}

// ---------------- host ----------------
extern "C" void kernel_launch(void* const* d_in, const int* in_sizes, int n_in,
                              void* d_out, int out_size) {
    (void)in_sizes; (void)n_in; (void)out_size;
    Params p;
    p.enc   = (const float*)d_in[0];
    p.caps  = (const int*)d_in[1];
    p.lens  = (const int*)d_in[2];
    p.eaw   = (const float*)d_in[3];
    p.eab   = (const float*)d_in[4];
    p.daw   = (const float*)d_in[5];
    p.dab   = (const float*)d_in[6];
    p.faw   = (const float*)d_in[7];
    p.fab   = (const float*)d_in[8];
    p.gw1   = (const float*)d_in[9];
    p.gb1   = (const float*)d_in[10];
    p.gw2   = (const float*)d_in[11];
    p.gb2   = (const float*)d_in[12];
    p.emb   = (const float*)d_in[13];
    p.g1wih = (const float*)d_in[14];
    p.g1whh = (const float*)d_in[15];
    p.g1bih = (const float*)d_in[16];
    p.g1bhh = (const float*)d_in[17];
    p.g2wih = (const float*)d_in[18];
    p.g2whh = (const float*)d_in[19];
    p.g2bih = (const float*)d_in[20];
    p.g2bhh = (const float*)d_in[21];
    p.pw    = (const float*)d_in[22];
    p.pb    = (const float*)d_in[23];
    p.ln1g  = (const float*)d_in[24];
    p.ln1b  = (const float*)d_in[25];
    p.ln2g  = (const float*)d_in[26];
    p.ln2b  = (const float*)d_in[27];
    p.fw1   = (const float*)d_in[28];
    p.fb1   = (const float*)d_in[29];
    p.fw2   = (const float*)d_in[30];
    p.fb2   = (const float*)d_in[31];
    p.out   = (float*)d_out;

    const int smem = 2 * (int)sizeof(SmemG) + (int)sizeof(SmemA);
    cudaFuncSetAttribute(decoder_persist, cudaFuncAttributeMaxDynamicSharedMemorySize, smem);
    decoder_persist<<<NBLK, NTHR, smem>>>(p);
}